// round 12
// baseline (speedup 1.0000x reference)
#include <cuda_runtime.h>
#include <cuda_fp16.h>

#define N_NODES 50000
#define N_EDGES 1600000
#define BATCH 4
#define T_STEPS 50
#define DT 0.02f

#define SQ 4                        // source quarters
#define SRC_CHUNK 12500             // N_NODES / SQ sources per chunk
#define N_ROWS (SQ * N_NODES)       // 200000 (row key = sq*N_NODES + tgt)
#define T_BLOCKS 37
#define TGT_BLK 1352                // ceil(N_NODES / T_BLOCKS); 37*1352 = 50024
#define SIM_CTAS (T_BLOCKS * SQ)    // 148 CTAs = one wave
#define K_ITERS 6                   // ceil(TGT_BLK / 256 quads)

#define SCAN_ELEMS 2048             // per scan block (512 thr x 4)
#define SCAN_NBLK 98                // ceil(N_ROWS / SCAN_ELEMS)

// ---------------- static device scratch (no allocations allowed) ----------------
__device__ __align__(16) int g_cnt[N_ROWS];
__device__ __align__(16) int g_rowtmp[N_ROWS];
__device__ int      g_bsum[SCAN_NBLK];
__device__ int      g_row[N_ROWS + 1];
__device__ int      g_cur[N_ROWS];
__device__ unsigned g_edges[N_EDGES];      // u16 src_local | f16 weight, sorted by (sq, tgt)
__device__ float2   g_ab[N_NODES];         // {alpha, alpha*bias}
__device__ float4   g_vstate[N_NODES];     // fp32 state, node-major x 4 batches
__device__ __align__(16) uint2 g_rates[2][N_NODES];   // half4 relu(v), double-buffered
__device__ float    g_part[SQ * N_NODES * BATCH];     // per-quarter partial sums

// ---------------- preprocessing ----------------

__global__ void zero_cnt_kernel() {
    int i = blockIdx.x * blockDim.x + threadIdx.x;
    if (i < N_ROWS) g_cnt[i] = 0;
}

__global__ void hist_kernel(const int* __restrict__ src, const int* __restrict__ tgt) {
    int e = blockIdx.x * blockDim.x + threadIdx.x;
    if (e < N_EDGES) {
        int row = (src[e] / SRC_CHUNK) * N_NODES + tgt[e];
        atomicAdd(&g_cnt[row], 1);
    }
}

// scan phase 1: per-block (512 thr x 4 elems) exclusive scan + block totals
__global__ void scan1_kernel() {
    __shared__ int wsum[16];
    int tid = threadIdx.x, lane = tid & 31, wi = tid >> 5;
    int i0 = blockIdx.x * SCAN_ELEMS + tid * 4;
    int4 c = make_int4(0, 0, 0, 0);
    if (i0 < N_ROWS) c = *(const int4*)&g_cnt[i0];   // N_ROWS % 4 == 0
    int tot = c.x + c.y + c.z + c.w;
    int incl = tot;
    #pragma unroll
    for (int d = 1; d < 32; d <<= 1) {
        int y = __shfl_up_sync(0xffffffffu, incl, d);
        if (lane >= d) incl += y;
    }
    if (lane == 31) wsum[wi] = incl;
    __syncthreads();
    if (wi == 0) {
        int s = (lane < 16) ? wsum[lane] : 0;
        int inc2 = s;
        #pragma unroll
        for (int d = 1; d < 32; d <<= 1) {
            int y = __shfl_up_sync(0xffffffffu, inc2, d);
            if (lane >= d) inc2 += y;
        }
        if (lane < 16) wsum[lane] = inc2 - s;
    }
    __syncthreads();
    int excl = wsum[wi] + (incl - tot);
    if (i0 < N_ROWS) {
        g_rowtmp[i0 + 0] = excl;
        g_rowtmp[i0 + 1] = excl + c.x;
        g_rowtmp[i0 + 2] = excl + c.x + c.y;
        g_rowtmp[i0 + 3] = excl + c.x + c.y + c.z;
    }
    if (tid == 511) g_bsum[blockIdx.x] = excl + tot;
}

// scan phase 2: exclusive scan of 98 block sums (1 block, 128 threads)
__global__ void scan2_kernel() {
    __shared__ int wsum[4];
    int tid = threadIdx.x, lane = tid & 31, wi = tid >> 5;
    int v = (tid < SCAN_NBLK) ? g_bsum[tid] : 0;
    int incl = v;
    #pragma unroll
    for (int d = 1; d < 32; d <<= 1) {
        int y = __shfl_up_sync(0xffffffffu, incl, d);
        if (lane >= d) incl += y;
    }
    if (lane == 31) wsum[wi] = incl;
    __syncthreads();
    if (wi == 0) {
        int s = (lane < 4) ? wsum[lane] : 0;
        int inc2 = s;
        #pragma unroll
        for (int d = 1; d < 8; d <<= 1) {
            int y = __shfl_up_sync(0xffffffffu, inc2, d);
            if (lane >= d) inc2 += y;
        }
        if (lane < 4) wsum[lane] = inc2 - s;
    }
    __syncthreads();
    if (tid < SCAN_NBLK) g_bsum[tid] = wsum[wi] + (incl - v);
}

// scan phase 3: add block offsets, produce g_row / g_cur
__global__ void scan3_kernel() {
    int i = blockIdx.x * blockDim.x + threadIdx.x;
    if (i < N_ROWS) {
        int v = g_rowtmp[i] + g_bsum[i >> 11];   // 2048 = 1<<11
        g_row[i] = v;
        g_cur[i] = v;
    }
    if (i == 0) g_row[N_ROWS] = N_EDGES;
}

__global__ void build_kernel(const int* __restrict__ src, const int* __restrict__ tgt,
                             const float* __restrict__ sign, const float* __restrict__ syn_cnt,
                             const float* __restrict__ syn_str) {
    int e = blockIdx.x * blockDim.x + threadIdx.x;
    if (e < N_EDGES) {
        float w = sign[e] * fmaxf(syn_cnt[e], 0.f) * fmaxf(syn_str[e], 0.f);
        __half hw = __float2half_rn(w);
        int s = src[e];
        int sq = s / SRC_CHUNK;
        unsigned rec = (unsigned)(s - sq * SRC_CHUNK)
                     | ((unsigned)__half_as_ushort(hw) << 16);
        int row = sq * N_NODES + tgt[e];
        int p = atomicAdd(&g_cur[row], 1);
        g_edges[p] = rec;
    }
}

__global__ void init_kernel(const float* __restrict__ bias, const float* __restrict__ tc) {
    int n = blockIdx.x * blockDim.x + threadIdx.x;
    if (n < N_NODES) {
        float tau = fmaxf(tc[n], DT);
        float a = DT / tau;
        float b = bias[n];
        g_ab[n] = make_float2(a, a * b);
        g_vstate[n] = make_float4(b, b, b, b);
        float r = fmaxf(b, 0.f);
        __half2 h = __floats2half2_rn(r, r);
        uint2 u; u.x = *(unsigned*)&h; u.y = u.x;
        g_rates[0][n] = u;
    }
}

// ---------------- sim kernel: smem-resident source chunk, LDS gathers ----------------
// CTA c: target block tb = c/4, source quarter sq = c&3. 1024 threads.
// Stage 100 KB rates chunk into smem, then quads (4 lanes) reduce (tgt, sq) rows,
// writing float4 partials. Gathers hit the smem crossbar, not L1tex wavefronts.
__global__ void __launch_bounds__(1024, 1) sim_kernel(int parity) {
    extern __shared__ uint2 sm_rates[];   // SRC_CHUNK entries = 100,000 B
    const int c = blockIdx.x;
    const int tb = c >> 2;
    const int sq = c & 3;
    const int tid = threadIdx.x;

    // stage rates chunk: 6250 uint4 = 100,000 B, coalesced
    {
        const uint4* __restrict__ gsrc = (const uint4*)(g_rates[parity] + sq * SRC_CHUNK);
        uint4* dst = (uint4*)sm_rates;
        #pragma unroll 1
        for (int i = tid; i < SRC_CHUNK / 2; i += 1024)
            dst[i] = __ldg(&gsrc[i]);
    }
    __syncthreads();

    const int quad = tid >> 2;   // 0..255
    const int sub  = tid & 3;

    #pragma unroll 1
    for (int k = 0; k < K_ITERS; k++) {
        int rr = k * 256 + quad;
        int n = tb * TGT_BLK + rr;
        bool valid = (rr < TGT_BLK) && (n < N_NODES);
        int beg = 0, end = 0;
        if (valid) {
            int key = sq * N_NODES + n;
            beg = g_row[key];
            end = g_row[key + 1];
        }
        __half2 a01 = __float2half2_rn(0.f);
        __half2 a23 = __float2half2_rn(0.f);
        for (int e = beg + sub; e < end; e += 4) {
            unsigned rec = __ldg(&g_edges[e]);
            uint2 r = sm_rates[rec & 0xFFFFu];           // LDS.64 random -> crossbar
            __half2 w2 = __half2half2(__ushort_as_half((unsigned short)(rec >> 16)));
            a01 = __hfma2(w2, *(__half2*)&r.x, a01);
            a23 = __hfma2(w2, *(__half2*)&r.y, a23);
        }
        float2 f01 = __half22float2(a01);
        float2 f23 = __half22float2(a23);
        #pragma unroll
        for (int d = 2; d; d >>= 1) {
            f01.x += __shfl_xor_sync(0xffffffffu, f01.x, d);
            f01.y += __shfl_xor_sync(0xffffffffu, f01.y, d);
            f23.x += __shfl_xor_sync(0xffffffffu, f23.x, d);
            f23.y += __shfl_xor_sync(0xffffffffu, f23.y, d);
        }
        if (valid && sub == 0)
            ((float4*)g_part)[sq * N_NODES + n] = make_float4(f01.x, f01.y, f23.x, f23.y);
    }
}

// ---------------- update kernel: sum 4 partials + Euler + output + rate pack ----------------
__global__ void __launch_bounds__(256) update_kernel(const float* __restrict__ x,
                                                     float* __restrict__ out,
                                                     int t, int parity) {
    int g = blockIdx.x * 256 + threadIdx.x;   // (n, b) flat
    if (g >= N_NODES * BATCH) return;
    int n = g >> 2, b = g & 3;
    float s = g_part[g]
            + g_part[1 * N_NODES * BATCH + g]
            + g_part[2 * N_NODES * BATCH + g]
            + g_part[3 * N_NODES * BATCH + g];
    float vold = ((const float*)g_vstate)[g];
    float2 ab = g_ab[n];
    int xi = (b * T_STEPS + t) * N_NODES + n;
    float xv = __ldg(&x[xi]);
    float vnew = vold + ab.x * (s + xv - vold) + ab.y;
    ((float*)g_vstate)[g] = vnew;
    float r = fmaxf(vnew, 0.f);
    out[xi] = r;
    ((__half*)g_rates[parity ^ 1])[g] = __float2half(r);
}

// ---------------- launch ----------------
extern "C" void kernel_launch(void* const* d_in, const int* in_sizes, int n_in,
                              void* d_out, int out_size) {
    const float* x            = (const float*)d_in[0];   // [B, T, N]
    const float* bias         = (const float*)d_in[1];   // [N]
    const float* time_const   = (const float*)d_in[2];   // [N]
    const float* sign         = (const float*)d_in[3];   // [E]
    const float* syn_count    = (const float*)d_in[4];   // [E]
    const float* syn_strength = (const float*)d_in[5];   // [E]
    const int*   src_idx      = (const int*)d_in[6];     // [E]
    const int*   tgt_idx      = (const int*)d_in[7];     // [E]
    float* out = (float*)d_out;                          // [B, T, N]

    static int smem_set = 0;
    if (!smem_set) {
        cudaFuncSetAttribute(sim_kernel, cudaFuncAttributeMaxDynamicSharedMemorySize,
                             SRC_CHUNK * (int)sizeof(uint2));
        smem_set = 1;
    }

    const int TB = 256;
    zero_cnt_kernel<<<(N_ROWS + TB - 1) / TB, TB>>>();
    hist_kernel<<<(N_EDGES + TB - 1) / TB, TB>>>(src_idx, tgt_idx);
    scan1_kernel<<<SCAN_NBLK, 512>>>();
    scan2_kernel<<<1, 128>>>();
    scan3_kernel<<<(N_ROWS + TB - 1) / TB, TB>>>();
    build_kernel<<<(N_EDGES + TB - 1) / TB, TB>>>(src_idx, tgt_idx, sign, syn_count, syn_strength);
    init_kernel<<<(N_NODES + TB - 1) / TB, TB>>>(bias, time_const);

    const int UPD_GRID = (N_NODES * BATCH + 255) / 256;   // 782
    for (int t = 0; t < T_STEPS; t++) {
        sim_kernel<<<SIM_CTAS, 1024, SRC_CHUNK * sizeof(uint2)>>>(t & 1);
        update_kernel<<<UPD_GRID, 256>>>(x, out, t, t & 1);
    }
}

// round 14
// speedup vs baseline: 1.2483x; 1.2483x over previous
#include <cuda_runtime.h>
#include <cuda_fp16.h>

#define N_NODES 50000
#define N_EDGES 1600000
#define HALF_N 25000              // src-half boundary: gather working set 25000*8B = 200KB < L1
#define N_ROWS2 (2 * N_NODES)     // row key = 2*tgt + (src >= HALF_N)
#define E_PAD_MAX 2300000         // exact worst: 1.6M + 100000*7
#define BATCH 4
#define T_STEPS 50
#define DT 0.02f

#define SCAN_ELEMS 2048           // per scan block (512 thr x 4)
#define SCAN_NBLK 49              // ceil(N_ROWS2 / SCAN_ELEMS)

// ---------------- static device scratch (no allocations allowed) ----------------
__device__ __align__(16) int g_cnt[N_ROWS2];
__device__ __align__(16) int g_rowtmp[N_ROWS2];
__device__ int      g_bsum[SCAN_NBLK];
__device__ int      g_row[N_ROWS2 + 1];
__device__ int      g_cur[N_ROWS2];
__device__ __align__(16) unsigned g_src32[E_PAD_MAX];  // src index (pad: 0)
__device__ __align__(16) unsigned g_wh2[E_PAD_MAX];    // half2{w,w}  (pad: 0)
__device__ float2   g_ab[N_NODES];         // {alpha, alpha*bias}
__device__ float4   g_vstate[N_NODES];     // fp32 state, node-major x 4 batches
__device__ __align__(16) uint2 g_rates[2][N_NODES];   // half4 relu(v), double-buffered

// ---------------- preprocessing ----------------

__global__ void zero_cnt_kernel() {
    int i = blockIdx.x * blockDim.x + threadIdx.x;
    if (i < N_ROWS2) g_cnt[i] = 0;
}

__global__ void fill_pad_kernel() {
    int i = blockIdx.x * blockDim.x + threadIdx.x;
    if (i < E_PAD_MAX) { g_src32[i] = 0u; g_wh2[i] = 0u; }
}

__global__ void hist_kernel(const int* __restrict__ src, const int* __restrict__ tgt) {
    int e = blockIdx.x * blockDim.x + threadIdx.x;
    if (e < N_EDGES) {
        int key = tgt[e] * 2 + (src[e] >= HALF_N ? 1 : 0);
        atomicAdd(&g_cnt[key], 1);
    }
}

// scan phase 1: per-block (512 thr x 4) exclusive scan of PAD8 counts + block totals
__global__ void scan1_kernel() {
    __shared__ int wsum[16];
    int tid = threadIdx.x, lane = tid & 31, wi = tid >> 5;
    int i0 = blockIdx.x * SCAN_ELEMS + tid * 4;
    int4 c = make_int4(0, 0, 0, 0);
    if (i0 < N_ROWS2) c = *(const int4*)&g_cnt[i0];   // N_ROWS2 % 4 == 0
    // pad each half-row count to a multiple of 8 edges
    c.x = (c.x + 7) & ~7;
    c.y = (c.y + 7) & ~7;
    c.z = (c.z + 7) & ~7;
    c.w = (c.w + 7) & ~7;
    int tot = c.x + c.y + c.z + c.w;
    int incl = tot;
    #pragma unroll
    for (int d = 1; d < 32; d <<= 1) {
        int y = __shfl_up_sync(0xffffffffu, incl, d);
        if (lane >= d) incl += y;
    }
    if (lane == 31) wsum[wi] = incl;
    __syncthreads();
    if (wi == 0) {
        int s = (lane < 16) ? wsum[lane] : 0;
        int inc2 = s;
        #pragma unroll
        for (int d = 1; d < 32; d <<= 1) {
            int y = __shfl_up_sync(0xffffffffu, inc2, d);
            if (lane >= d) inc2 += y;
        }
        if (lane < 16) wsum[lane] = inc2 - s;
    }
    __syncthreads();
    int excl = wsum[wi] + (incl - tot);
    if (i0 < N_ROWS2) {
        g_rowtmp[i0 + 0] = excl;
        g_rowtmp[i0 + 1] = excl + c.x;
        g_rowtmp[i0 + 2] = excl + c.x + c.y;
        g_rowtmp[i0 + 3] = excl + c.x + c.y + c.z;
    }
    if (tid == 511) g_bsum[blockIdx.x] = excl + tot;
}

// scan phase 2: exclusive scan of block sums (1 block, 128 threads)
__global__ void scan2_kernel() {
    __shared__ int wsum[4];
    int tid = threadIdx.x, lane = tid & 31, wi = tid >> 5;
    int v = (tid < SCAN_NBLK) ? g_bsum[tid] : 0;
    int incl = v;
    #pragma unroll
    for (int d = 1; d < 32; d <<= 1) {
        int y = __shfl_up_sync(0xffffffffu, incl, d);
        if (lane >= d) incl += y;
    }
    if (lane == 31) wsum[wi] = incl;
    __syncthreads();
    if (wi == 0) {
        int s = (lane < 4) ? wsum[lane] : 0;
        int inc2 = s;
        #pragma unroll
        for (int d = 1; d < 8; d <<= 1) {
            int y = __shfl_up_sync(0xffffffffu, inc2, d);
            if (lane >= d) inc2 += y;
        }
        if (lane < 4) wsum[lane] = inc2 - s;
    }
    __syncthreads();
    if (tid < SCAN_NBLK) g_bsum[tid] = wsum[wi] + (incl - v);
}

// scan phase 3: add block offsets, produce g_row / g_cur (+ padded total)
__global__ void scan3_kernel() {
    int i = blockIdx.x * blockDim.x + threadIdx.x;
    if (i < N_ROWS2) {
        int v = g_rowtmp[i] + g_bsum[i >> 11];   // 2048 = 1<<11
        g_row[i] = v;
        g_cur[i] = v;
        if (i == N_ROWS2 - 1)
            g_row[N_ROWS2] = v + ((g_cnt[i] + 7) & ~7);
    }
}

__global__ void build_kernel(const int* __restrict__ src, const int* __restrict__ tgt,
                             const float* __restrict__ sign, const float* __restrict__ syn_cnt,
                             const float* __restrict__ syn_str) {
    int e = blockIdx.x * blockDim.x + threadIdx.x;
    if (e < N_EDGES) {
        float w = sign[e] * fmaxf(syn_cnt[e], 0.f) * fmaxf(syn_str[e], 0.f);
        __half2 h2 = __half2half2(__float2half_rn(w));
        int s = src[e];
        int key = tgt[e] * 2 + (s >= HALF_N ? 1 : 0);
        int p = atomicAdd(&g_cur[key], 1);
        g_src32[p] = (unsigned)s;
        g_wh2[p] = *(unsigned*)&h2;
    }
}

__global__ void init_kernel(const float* __restrict__ bias, const float* __restrict__ tc) {
    int n = blockIdx.x * blockDim.x + threadIdx.x;
    if (n < N_NODES) {
        float tau = fmaxf(tc[n], DT);
        float a = DT / tau;
        float b = bias[n];
        g_ab[n] = make_float2(a, a * b);
        g_vstate[n] = make_float4(b, b, b, b);
        float r = fmaxf(b, 0.f);
        __half2 h = __floats2half2_rn(r, r);
        uint2 u; u.x = *(unsigned*)&h; u.y = u.x;
        g_rates[0][n] = u;
    }
}

// one 4-edge chunk for one lane: 2x LDG.128 (streaming) + 4 gathers + 8 HFMA2
__device__ __forceinline__ void chunk4(const uint2* __restrict__ rin, int e,
                                       __half2& a01, __half2& a23) {
    uint4 s4 = __ldcs((const uint4*)(g_src32 + e));
    uint4 w4 = __ldcs((const uint4*)(g_wh2 + e));
    uint2 r0 = __ldg(&rin[s4.x]);
    uint2 r1 = __ldg(&rin[s4.y]);
    uint2 r2 = __ldg(&rin[s4.z]);
    uint2 r3 = __ldg(&rin[s4.w]);
    a01 = __hfma2(*(__half2*)&w4.x, *(__half2*)&r0.x, a01);
    a23 = __hfma2(*(__half2*)&w4.x, *(__half2*)&r0.y, a23);
    a01 = __hfma2(*(__half2*)&w4.y, *(__half2*)&r1.x, a01);
    a23 = __hfma2(*(__half2*)&w4.y, *(__half2*)&r1.y, a23);
    a01 = __hfma2(*(__half2*)&w4.z, *(__half2*)&r2.x, a01);
    a23 = __hfma2(*(__half2*)&w4.z, *(__half2*)&r2.y, a23);
    a01 = __hfma2(*(__half2*)&w4.w, *(__half2*)&r3.x, a01);
    a23 = __hfma2(*(__half2*)&w4.w, *(__half2*)&r3.y, a23);
}

// accumulate one half-row (padded to x8 edges); 2 lanes (sub), 4 edges/lane/granule
__device__ __forceinline__ void accum_half(const uint2* __restrict__ rin,
                                           int beg, int end, int sub,
                                           float2& f01, float2& f23) {
    const __half2 hz = __float2half2_rn(0.f);
    int e = beg + (sub << 2);
    while (e + 8 < end) {          // >= 2 granules remain
        __half2 a01 = hz, a23 = hz;
        chunk4(rin, e, a01, a23);
        chunk4(rin, e + 8, a01, a23);
        float2 p01 = __half22float2(a01);
        float2 p23 = __half22float2(a23);
        f01.x += p01.x; f01.y += p01.y;
        f23.x += p23.x; f23.y += p23.y;
        e += 16;
    }
    if (e < end) {                 // last granule
        __half2 a01 = hz, a23 = hz;
        chunk4(rin, e, a01, a23);
        float2 p01 = __half22float2(a01);
        float2 p23 = __half22float2(a23);
        f01.x += p01.x; f01.y += p01.y;
        f23.x += p23.x; f23.y += p23.y;
    }
}

// ---------------- per-step kernel ----------------
// CTA = 256 threads = 128 nodes (2 lanes/node). Grid = 391.
// Each target row is split into src-halves; CTA runs phase A (src<25000) for all
// its rows, then phase B. Per phase the gather footprint is 200KB -> L1-resident.
// Edge/x streams use __ldcs so they don't evict the rates from L1.
__global__ void __launch_bounds__(256, 6) step_kernel(const float* __restrict__ x,
                                                      float* __restrict__ out,
                                                      int t, int parity) {
    const int node0 = blockIdx.x * 128;
    const int tid = threadIdx.x;
    const int sub = tid & 1;
    const int pair = tid >> 1;       // node within CTA, 0..127
    const int n = node0 + pair;

    const uint2* __restrict__ rin = g_rates[parity];
    __half* __restrict__ rout = (__half*)g_rates[parity ^ 1];

    int begA = 0, endA = 0, endB = 0;
    if (n < N_NODES) {
        begA = g_row[2 * n];
        endA = g_row[2 * n + 1];
        endB = g_row[2 * n + 2];
    }

    float2 f01 = make_float2(0.f, 0.f);
    float2 f23 = make_float2(0.f, 0.f);

    accum_half(rin, begA, endA, sub, f01, f23);   // phase A: src in [0, 25000)
    accum_half(rin, endA, endB, sub, f01, f23);   // phase B: src in [25000, 50000)

    // pair reduction (1 round)
    f01.x += __shfl_xor_sync(0xffffffffu, f01.x, 1);
    f01.y += __shfl_xor_sync(0xffffffffu, f01.y, 1);
    f23.x += __shfl_xor_sync(0xffffffffu, f23.x, 1);
    f23.y += __shfl_xor_sync(0xffffffffu, f23.y, 1);

    __shared__ float sh[512];   // [node_in_cta][batch]
    if (sub == 0) {
        sh[pair * 4 + 0] = f01.x;
        sh[pair * 4 + 1] = f01.y;
        sh[pair * 4 + 2] = f23.x;
        sh[pair * 4 + 3] = f23.y;
    }
    __syncthreads();

    // epilogue: 256 threads cover 128 nodes x 4 batches (2 elems each), coalesced
    #pragma unroll
    for (int k = tid; k < 512; k += 256) {
        int j = k >> 2;
        int b = k & 3;
        int nn = node0 + j;
        if (nn < N_NODES) {
            float vold = ((const float*)g_vstate)[node0 * 4 + k];
            float s    = sh[k];
            float2 ab  = g_ab[nn];
            int   xi   = (b * T_STEPS + t) * N_NODES + nn;
            float xv   = __ldcs(&x[xi]);
            float vnew = vold + ab.x * (s + xv - vold) + ab.y;
            ((float*)g_vstate)[node0 * 4 + k] = vnew;
            float r = fmaxf(vnew, 0.f);
            out[xi] = r;
            rout[node0 * 4 + k] = __float2half(r);
        }
    }
}

// ---------------- launch ----------------
extern "C" void kernel_launch(void* const* d_in, const int* in_sizes, int n_in,
                              void* d_out, int out_size) {
    const float* x            = (const float*)d_in[0];   // [B, T, N]
    const float* bias         = (const float*)d_in[1];   // [N]
    const float* time_const   = (const float*)d_in[2];   // [N]
    const float* sign         = (const float*)d_in[3];   // [E]
    const float* syn_count    = (const float*)d_in[4];   // [E]
    const float* syn_strength = (const float*)d_in[5];   // [E]
    const int*   src_idx      = (const int*)d_in[6];     // [E]
    const int*   tgt_idx      = (const int*)d_in[7];     // [E]
    float* out = (float*)d_out;                          // [B, T, N]

    const int TB = 256;
    zero_cnt_kernel<<<(N_ROWS2 + TB - 1) / TB, TB>>>();
    fill_pad_kernel<<<(E_PAD_MAX + TB - 1) / TB, TB>>>();
    hist_kernel<<<(N_EDGES + TB - 1) / TB, TB>>>(src_idx, tgt_idx);
    scan1_kernel<<<SCAN_NBLK, 512>>>();
    scan2_kernel<<<1, 128>>>();
    scan3_kernel<<<(N_ROWS2 + TB - 1) / TB, TB>>>();
    build_kernel<<<(N_EDGES + TB - 1) / TB, TB>>>(src_idx, tgt_idx, sign, syn_count, syn_strength);
    init_kernel<<<(N_NODES + TB - 1) / TB, TB>>>(bias, time_const);

    const int STEP_GRID = (N_NODES + 127) / 128;   // 391
    for (int t = 0; t < T_STEPS; t++) {
        step_kernel<<<STEP_GRID, 256>>>(x, out, t, t & 1);
    }
}

// round 15
// speedup vs baseline: 1.5846x; 1.2695x over previous
#include <cuda_runtime.h>
#include <cuda_fp16.h>

#define N_NODES 50000
#define N_EDGES 1600000
#define SQ 4                          // source quarters
#define SRC_CHUNK 12500               // sources per chunk; 12500*8B = 100,000B smem
#define N_ROWS (SQ * N_NODES)         // 200000; row key = q*N_NODES + tgt
#define E_PAD_MAX 2200000             // worst: 1.6M + 200000*3 (pad to x4)
#define BATCH 4
#define T_STEPS 50
#define DT 0.02f
#define T_BLOCKS 37
#define TGT_BLK 1352                  // 37*1352 = 50024 >= N_NODES
#define SIM_CTAS (T_BLOCKS * SQ)      // 148 = one wave
#define SMEM_BYTES (SRC_CHUNK * 8)    // 100,000

#define SCAN_ELEMS 2048               // per scan block (512 thr x 4)
#define SCAN_NBLK 98                  // ceil(N_ROWS / SCAN_ELEMS)

// ---------------- static device scratch (no allocations allowed) ----------------
__device__ __align__(16) int g_cnt[N_ROWS];
__device__ __align__(16) int g_rowtmp[N_ROWS];
__device__ int      g_bsum[SCAN_NBLK];
__device__ int      g_row[N_ROWS + 1];
__device__ int      g_cur[N_ROWS];
__device__ __align__(16) unsigned g_edges[E_PAD_MAX];  // u16 src_local | f16 w (pad: 0)
__device__ float2   g_ab[N_NODES];          // {alpha, alpha*bias}
__device__ float4   g_vstate[N_NODES];      // fp32 state, node-major x 4 batches
__device__ __align__(16) uint2 g_rates[2][N_NODES];    // half4 relu(v), double-buffered
__device__ __align__(16) float g_part[SQ * N_NODES * BATCH];  // per-quarter partials

// ---------------- preprocessing ----------------

__global__ void zero_cnt_kernel() {
    int i = blockIdx.x * blockDim.x + threadIdx.x;
    if (i < N_ROWS) g_cnt[i] = 0;
}

__global__ void fill_pad_kernel() {
    int i = blockIdx.x * blockDim.x + threadIdx.x;
    if (i < E_PAD_MAX) g_edges[i] = 0u;
}

__global__ void hist_kernel(const int* __restrict__ src, const int* __restrict__ tgt) {
    int e = blockIdx.x * blockDim.x + threadIdx.x;
    if (e < N_EDGES) {
        int key = (src[e] / SRC_CHUNK) * N_NODES + tgt[e];
        atomicAdd(&g_cnt[key], 1);
    }
}

// scan phase 1: per-block (512 thr x 4) exclusive scan of PAD4 counts + block totals
__global__ void scan1_kernel() {
    __shared__ int wsum[16];
    int tid = threadIdx.x, lane = tid & 31, wi = tid >> 5;
    int i0 = blockIdx.x * SCAN_ELEMS + tid * 4;
    int4 c = make_int4(0, 0, 0, 0);
    if (i0 < N_ROWS) c = *(const int4*)&g_cnt[i0];   // N_ROWS % 4 == 0
    // pad each row count to a multiple of 4 edges
    c.x = (c.x + 3) & ~3;
    c.y = (c.y + 3) & ~3;
    c.z = (c.z + 3) & ~3;
    c.w = (c.w + 3) & ~3;
    int tot = c.x + c.y + c.z + c.w;
    int incl = tot;
    #pragma unroll
    for (int d = 1; d < 32; d <<= 1) {
        int y = __shfl_up_sync(0xffffffffu, incl, d);
        if (lane >= d) incl += y;
    }
    if (lane == 31) wsum[wi] = incl;
    __syncthreads();
    if (wi == 0) {
        int s = (lane < 16) ? wsum[lane] : 0;
        int inc2 = s;
        #pragma unroll
        for (int d = 1; d < 32; d <<= 1) {
            int y = __shfl_up_sync(0xffffffffu, inc2, d);
            if (lane >= d) inc2 += y;
        }
        if (lane < 16) wsum[lane] = inc2 - s;
    }
    __syncthreads();
    int excl = wsum[wi] + (incl - tot);
    if (i0 < N_ROWS) {
        g_rowtmp[i0 + 0] = excl;
        g_rowtmp[i0 + 1] = excl + c.x;
        g_rowtmp[i0 + 2] = excl + c.x + c.y;
        g_rowtmp[i0 + 3] = excl + c.x + c.y + c.z;
    }
    if (tid == 511) g_bsum[blockIdx.x] = excl + tot;
}

// scan phase 2: exclusive scan of block sums (1 block, 128 threads)
__global__ void scan2_kernel() {
    __shared__ int wsum[4];
    int tid = threadIdx.x, lane = tid & 31, wi = tid >> 5;
    int v = (tid < SCAN_NBLK) ? g_bsum[tid] : 0;
    int incl = v;
    #pragma unroll
    for (int d = 1; d < 32; d <<= 1) {
        int y = __shfl_up_sync(0xffffffffu, incl, d);
        if (lane >= d) incl += y;
    }
    if (lane == 31) wsum[wi] = incl;
    __syncthreads();
    if (wi == 0) {
        int s = (lane < 4) ? wsum[lane] : 0;
        int inc2 = s;
        #pragma unroll
        for (int d = 1; d < 8; d <<= 1) {
            int y = __shfl_up_sync(0xffffffffu, inc2, d);
            if (lane >= d) inc2 += y;
        }
        if (lane < 4) wsum[lane] = inc2 - s;
    }
    __syncthreads();
    if (tid < SCAN_NBLK) g_bsum[tid] = wsum[wi] + (incl - v);
}

// scan phase 3: add block offsets -> g_row / g_cur (+ padded total)
__global__ void scan3_kernel() {
    int i = blockIdx.x * blockDim.x + threadIdx.x;
    if (i < N_ROWS) {
        int v = g_rowtmp[i] + g_bsum[i >> 11];   // 2048 = 1<<11
        g_row[i] = v;
        g_cur[i] = v;
        if (i == N_ROWS - 1)
            g_row[N_ROWS] = v + ((g_cnt[i] + 3) & ~3);
    }
}

__global__ void build_kernel(const int* __restrict__ src, const int* __restrict__ tgt,
                             const float* __restrict__ sign, const float* __restrict__ syn_cnt,
                             const float* __restrict__ syn_str) {
    int e = blockIdx.x * blockDim.x + threadIdx.x;
    if (e < N_EDGES) {
        float w = sign[e] * fmaxf(syn_cnt[e], 0.f) * fmaxf(syn_str[e], 0.f);
        int s = src[e];
        int q = s / SRC_CHUNK;
        unsigned rec = (unsigned)(s - q * SRC_CHUNK)
                     | ((unsigned)__half_as_ushort(__float2half_rn(w)) << 16);
        int key = q * N_NODES + tgt[e];
        int p = atomicAdd(&g_cur[key], 1);
        g_edges[p] = rec;
    }
}

__global__ void init_kernel(const float* __restrict__ bias, const float* __restrict__ tc) {
    int n = blockIdx.x * blockDim.x + threadIdx.x;
    if (n < N_NODES) {
        float tau = fmaxf(tc[n], DT);
        float a = DT / tau;
        float b = bias[n];
        g_ab[n] = make_float2(a, a * b);
        g_vstate[n] = make_float4(b, b, b, b);
        float r = fmaxf(b, 0.f);
        __half2 h = __floats2half2_rn(r, r);
        uint2 u; u.x = *(unsigned*)&h; u.y = u.x;
        g_rates[0][n] = u;
    }
}

// process 4 packed edge recs: 4 LDS.64 gathers + decode + 8 HFMA2
__device__ __forceinline__ void proc4(const uint2* __restrict__ sm, uint4 r,
                                      __half2& a01, __half2& a23) {
    uint2 v0 = sm[r.x & 0xFFFFu];
    uint2 v1 = sm[r.y & 0xFFFFu];
    uint2 v2 = sm[r.z & 0xFFFFu];
    uint2 v3 = sm[r.w & 0xFFFFu];
    __half2 w0 = __half2half2(__ushort_as_half((unsigned short)(r.x >> 16)));
    __half2 w1 = __half2half2(__ushort_as_half((unsigned short)(r.y >> 16)));
    __half2 w2 = __half2half2(__ushort_as_half((unsigned short)(r.z >> 16)));
    __half2 w3 = __half2half2(__ushort_as_half((unsigned short)(r.w >> 16)));
    a01 = __hfma2(w0, *(__half2*)&v0.x, a01);
    a23 = __hfma2(w0, *(__half2*)&v0.y, a23);
    a01 = __hfma2(w1, *(__half2*)&v1.x, a01);
    a23 = __hfma2(w1, *(__half2*)&v1.y, a23);
    a01 = __hfma2(w2, *(__half2*)&v2.x, a01);
    a23 = __hfma2(w2, *(__half2*)&v2.y, a23);
    a01 = __hfma2(w3, *(__half2*)&v3.x, a01);
    a23 = __hfma2(w3, *(__half2*)&v3.y, a23);
}

// ---------------- sim kernel: smem-resident source quarter, LDS gathers ----------------
// CTA bx: target block tb = bx>>2, quarter q = bx&3. 1024 threads, 100KB smem.
// Stage quarter's rates (coalesced), then 1 lane per (tgt, q) row; rows padded to
// x4 so each granule is one LDG.128 of 4 recs; 2 granules unrolled for MLP.
__global__ void __launch_bounds__(1024, 1) sim_kernel(int parity) {
    extern __shared__ __align__(16) uint2 sm_rates[];   // SRC_CHUNK entries
    const int bx = blockIdx.x;
    const int tb = bx >> 2;
    const int q  = bx & 3;
    const int tid = threadIdx.x;

    // stage 100,000 B = 6250 uint4, coalesced
    {
        const uint4* __restrict__ gsrc = (const uint4*)(g_rates[parity] + q * SRC_CHUNK);
        uint4* dst = (uint4*)sm_rates;
        #pragma unroll 1
        for (int i = tid; i < SRC_CHUNK / 2; i += 1024)
            dst[i] = __ldg(&gsrc[i]);
    }
    __syncthreads();

    const __half2 hz = __float2half2_rn(0.f);

    #pragma unroll 1
    for (int j = tid; j < TGT_BLK; j += 1024) {
        int n = tb * TGT_BLK + j;
        if (n >= N_NODES) break;
        int key = q * N_NODES + n;
        int beg = g_row[key];
        int end = g_row[key + 1];

        float2 f01 = make_float2(0.f, 0.f);
        float2 f23 = make_float2(0.f, 0.f);
        int e = beg;
        while (e + 4 < end) {        // two granules available
            uint4 ra = __ldg((const uint4*)&g_edges[e]);
            uint4 rb = __ldg((const uint4*)&g_edges[e + 4]);
            __half2 a01 = hz, a23 = hz;
            proc4(sm_rates, ra, a01, a23);
            proc4(sm_rates, rb, a01, a23);
            float2 p01 = __half22float2(a01);
            float2 p23 = __half22float2(a23);
            f01.x += p01.x; f01.y += p01.y;
            f23.x += p23.x; f23.y += p23.y;
            e += 8;
        }
        if (e < end) {               // final granule
            uint4 ra = __ldg((const uint4*)&g_edges[e]);
            __half2 a01 = hz, a23 = hz;
            proc4(sm_rates, ra, a01, a23);
            float2 p01 = __half22float2(a01);
            float2 p23 = __half22float2(a23);
            f01.x += p01.x; f01.y += p01.y;
            f23.x += p23.x; f23.y += p23.y;
        }
        ((float4*)g_part)[q * N_NODES + n] = make_float4(f01.x, f01.y, f23.x, f23.y);
    }
}

// ---------------- update kernel: sum 4 partials + Euler + output + rate pack ----------------
__global__ void __launch_bounds__(256) update_kernel(const float* __restrict__ x,
                                                     float* __restrict__ out,
                                                     int t, int parity) {
    int g = blockIdx.x * 256 + threadIdx.x;   // (n, b) flat
    if (g >= N_NODES * BATCH) return;
    int n = g >> 2, b = g & 3;
    float s = g_part[g]
            + g_part[1 * N_NODES * BATCH + g]
            + g_part[2 * N_NODES * BATCH + g]
            + g_part[3 * N_NODES * BATCH + g];
    float vold = ((const float*)g_vstate)[g];
    float2 ab = g_ab[n];
    int xi = (b * T_STEPS + t) * N_NODES + n;
    float xv = __ldg(&x[xi]);
    float vnew = vold + ab.x * (s + xv - vold) + ab.y;
    ((float*)g_vstate)[g] = vnew;
    float r = fmaxf(vnew, 0.f);
    out[xi] = r;
    ((__half*)g_rates[parity ^ 1])[g] = __float2half(r);
}

// ---------------- launch ----------------
extern "C" void kernel_launch(void* const* d_in, const int* in_sizes, int n_in,
                              void* d_out, int out_size) {
    const float* x            = (const float*)d_in[0];   // [B, T, N]
    const float* bias         = (const float*)d_in[1];   // [N]
    const float* time_const   = (const float*)d_in[2];   // [N]
    const float* sign         = (const float*)d_in[3];   // [E]
    const float* syn_count    = (const float*)d_in[4];   // [E]
    const float* syn_strength = (const float*)d_in[5];   // [E]
    const int*   src_idx      = (const int*)d_in[6];     // [E]
    const int*   tgt_idx      = (const int*)d_in[7];     // [E]
    float* out = (float*)d_out;                          // [B, T, N]

    static int smem_set = 0;
    if (!smem_set) {
        cudaFuncSetAttribute(sim_kernel, cudaFuncAttributeMaxDynamicSharedMemorySize,
                             SMEM_BYTES);
        smem_set = 1;
    }

    const int TB = 256;
    zero_cnt_kernel<<<(N_ROWS + TB - 1) / TB, TB>>>();
    fill_pad_kernel<<<(E_PAD_MAX + TB - 1) / TB, TB>>>();
    hist_kernel<<<(N_EDGES + TB - 1) / TB, TB>>>(src_idx, tgt_idx);
    scan1_kernel<<<SCAN_NBLK, 512>>>();
    scan2_kernel<<<1, 128>>>();
    scan3_kernel<<<(N_ROWS + TB - 1) / TB, TB>>>();
    build_kernel<<<(N_EDGES + TB - 1) / TB, TB>>>(src_idx, tgt_idx, sign, syn_count, syn_strength);
    init_kernel<<<(N_NODES + TB - 1) / TB, TB>>>(bias, time_const);

    const int UPD_GRID = (N_NODES * BATCH + 255) / 256;   // 782
    for (int t = 0; t < T_STEPS; t++) {
        sim_kernel<<<SIM_CTAS, 1024, SMEM_BYTES>>>(t & 1);
        update_kernel<<<UPD_GRID, 256>>>(x, out, t, t & 1);
    }
}